// round 3
// baseline (speedup 1.0000x reference)
#include <cuda_runtime.h>
#include <math.h>

// ---------------- problem constants ----------------
#define Lq    12000
#define INDIM 1024
#define Dm    128
#define EDm   256
#define Nst   16
#define DTm   8
#define TCH   64
#define NCH   ((Lq + TCH - 1) / TCH)     // 188
#define NPOOL ((Lq + 127) / 128)         // 94
#define EPSV  1e-5f

// ---------------- scratch (static device memory; no allocs) ----------------
__device__ float g_h[Lq * Dm];
__device__ float g_hn[Lq * Dm];
__device__ float g_hln[Lq * Dm];
__device__ float g_xb[Lq * EDm];
__device__ float g_z[Lq * EDm];
__device__ float g_xc[Lq * EDm];
__device__ float g_dbl[Lq * 40];
__device__ float g_delta[Lq * EDm];
__device__ float g_y[Lq * EDm];
__device__ float g_ta[Lq * Dm];
__device__ float g_att[Lq];
__device__ float g_S[NCH * EDm * Nst];
__device__ float g_sumd[NCH * EDm];
__device__ float g_carry[NCH * EDm * Nst];
__device__ float g_part[NPOOL * Dm];
__device__ float g_stat[2];

// ---------------- helpers ----------------
__device__ __forceinline__ float gelu_exact(float x) {
    return 0.5f * x * (1.f + erff(x * 0.7071067811865475f));
}
__device__ __forceinline__ float siluf(float x) {
    return x / (1.f + __expf(-x));
}

// ---------------- tiled fp32 GEMM: C = epi(A[MxK] @ W[KxN]) ----------------
// BM=64, BN=64, BK=16, 128 threads, 8x4 microtile. K must be multiple of 16.
// epi: 0 plain store, 1 +bias+GELU, 2 split xb/z (N=512), 3 residual add, 4 +bias+tanh
__global__ __launch_bounds__(128)
void gemm64(const float* __restrict__ A, const float* __restrict__ W,
            const float* __restrict__ bias, float* __restrict__ out,
            float* __restrict__ out2, int M, int N, int K, int epi)
{
    __shared__ float As[16][64];
    __shared__ float Bs[16][64];

    const int tid = threadIdx.x;
    const int tx = tid & 15;   // 0..15  -> col group (4 cols)
    const int ty = tid >> 4;   // 0..7   -> row group (8 rows)
    const int row0 = blockIdx.y * 64;
    const int col0 = blockIdx.x * 64;

    float acc[8][4];
#pragma unroll
    for (int i = 0; i < 8; i++)
#pragma unroll
        for (int j = 0; j < 4; j++) acc[i][j] = 0.f;

    const int la_row = tid >> 2;          // 0..31
    const int la_k   = (tid & 3) * 4;     // 0,4,8,12
    const int lb_row = tid >> 4;          // 0..7
    const int lb_col = (tid & 15) * 4;    // 0..60

    for (int k0 = 0; k0 < K; k0 += 16) {
#pragma unroll
        for (int p = 0; p < 2; p++) {
            int r = la_row + p * 32;
            int gm = row0 + r;
            float4 v = make_float4(0.f, 0.f, 0.f, 0.f);
            if (gm < M) v = *(const float4*)(A + (size_t)gm * K + k0 + la_k);
            As[la_k + 0][r] = v.x;
            As[la_k + 1][r] = v.y;
            As[la_k + 2][r] = v.z;
            As[la_k + 3][r] = v.w;
        }
#pragma unroll
        for (int p = 0; p < 2; p++) {
            int r = lb_row + p * 8;
            int gn = col0 + lb_col;
            float4 v = make_float4(0.f, 0.f, 0.f, 0.f);
            if (gn < N) v = *(const float4*)(W + (size_t)(k0 + r) * N + gn);
            *(float4*)&Bs[r][lb_col] = v;
        }
        __syncthreads();
#pragma unroll
        for (int kk = 0; kk < 16; kk++) {
            float4 a0 = *(const float4*)&As[kk][ty * 8];
            float4 a1 = *(const float4*)&As[kk][ty * 8 + 4];
            float4 b  = *(const float4*)&Bs[kk][tx * 4];
            float av[8] = {a0.x, a0.y, a0.z, a0.w, a1.x, a1.y, a1.z, a1.w};
            float bv[4] = {b.x, b.y, b.z, b.w};
#pragma unroll
            for (int i = 0; i < 8; i++)
#pragma unroll
                for (int j = 0; j < 4; j++)
                    acc[i][j] = fmaf(av[i], bv[j], acc[i][j]);
        }
        __syncthreads();
    }

#pragma unroll
    for (int i = 0; i < 8; i++) {
        int gm = row0 + ty * 8 + i;
        if (gm >= M) continue;
#pragma unroll
        for (int j = 0; j < 4; j++) {
            int gn = col0 + tx * 4 + j;
            if (gn >= N) continue;
            float v = acc[i][j];
            if (epi == 0) {
                out[(size_t)gm * N + gn] = v;
            } else if (epi == 1) {
                v += bias[gn];
                out[(size_t)gm * N + gn] = gelu_exact(v);
            } else if (epi == 2) {
                if (gn < EDm) out[(size_t)gm * EDm + gn] = v;
                else          out2[(size_t)gm * EDm + (gn - EDm)] = v;
            } else if (epi == 3) {
                out[(size_t)gm * N + gn] += v;
            } else { // 4
                out[(size_t)gm * N + gn] = tanhf(v + bias[gn]);
            }
        }
    }
}

// ---------------- RMSNorm over D=128 (one block per row) ----------------
__global__ __launch_bounds__(128)
void rmsnorm_kernel(const float* __restrict__ h, const float* __restrict__ w,
                    float* __restrict__ out)
{
    int t = blockIdx.x;
    int d = threadIdx.x;
    float v = h[(size_t)t * Dm + d];
    float ss = v * v;
#pragma unroll
    for (int o = 16; o > 0; o >>= 1) ss += __shfl_xor_sync(0xffffffffu, ss, o);
    __shared__ float sm[4];
    if ((d & 31) == 0) sm[d >> 5] = ss;
    __syncthreads();
    float tot = sm[0] + sm[1] + sm[2] + sm[3];
    out[(size_t)t * Dm + d] = v * rsqrtf(tot * (1.f / Dm) + EPSV) * w[d];
}

// ---------------- LayerNorm over D=128 ----------------
__global__ __launch_bounds__(128)
void layernorm_kernel(const float* __restrict__ h, const float* __restrict__ w,
                      const float* __restrict__ b, float* __restrict__ out)
{
    int t = blockIdx.x;
    int d = threadIdx.x;
    float v = h[(size_t)t * Dm + d];
    float s = v, ss = v * v;
#pragma unroll
    for (int o = 16; o > 0; o >>= 1) {
        s  += __shfl_xor_sync(0xffffffffu, s, o);
        ss += __shfl_xor_sync(0xffffffffu, ss, o);
    }
    __shared__ float sm1[4], sm2[4];
    if ((d & 31) == 0) { sm1[d >> 5] = s; sm2[d >> 5] = ss; }
    __syncthreads();
    float S = sm1[0] + sm1[1] + sm1[2] + sm1[3];
    float SS = sm2[0] + sm2[1] + sm2[2] + sm2[3];
    float m = S * (1.f / Dm);
    float var = SS * (1.f / Dm) - m * m;
    out[(size_t)t * Dm + d] = (v - m) * rsqrtf(var + EPSV) * w[d] + b[d];
}

// ---------------- causal depthwise conv (K=4) + SiLU ----------------
__global__ __launch_bounds__(256)
void conv_kernel(const float* __restrict__ xb, const float* __restrict__ w,
                 const float* __restrict__ b, float* __restrict__ xc)
{
    int t = blockIdx.x;
    int e = threadIdx.x;
    float4 wv = ((const float4*)w)[e];   // w[e][0..3]
    float acc = b[e];
    const float* col = xb + e;
    if (t >= 3) acc = fmaf(col[(size_t)(t - 3) * EDm], wv.x, acc);
    if (t >= 2) acc = fmaf(col[(size_t)(t - 2) * EDm], wv.y, acc);
    if (t >= 1) acc = fmaf(col[(size_t)(t - 1) * EDm], wv.z, acc);
    acc = fmaf(col[(size_t)t * EDm], wv.w, acc);
    xc[(size_t)t * EDm + e] = siluf(acc);
}

// ---------------- delta = softplus(dlt @ dt_w + dt_b) ----------------
__global__ __launch_bounds__(256)
void dt_kernel(const float* __restrict__ dbl, const float* __restrict__ dtw,
               const float* __restrict__ dtb, float* __restrict__ delta)
{
    int t = blockIdx.x;
    int e = threadIdx.x;
    __shared__ float dl[DTm];
    if (e < DTm) dl[e] = dbl[(size_t)t * 40 + e];
    __syncthreads();
    float acc = dtb[e];
#pragma unroll
    for (int k = 0; k < DTm; k++) acc = fmaf(dl[k], dtw[k * EDm + e], acc);
    float dv = (acc > 20.f) ? acc : log1pf(expf(acc));
    delta[(size_t)t * EDm + e] = dv;
}

// ---------------- scan phase 1: per-chunk local end-state + sum(delta) ----------------
__global__ __launch_bounds__(256)
void scan1_kernel(const float* __restrict__ delta, const float* __restrict__ xc,
                  const float* __restrict__ dbl, const float* __restrict__ Alog,
                  float* __restrict__ Sout, float* __restrict__ sumdOut)
{
    int c = blockIdx.x;
    int e = threadIdx.x;
    int t0 = c * TCH;
    int tn = min(TCH, Lq - t0);

    __shared__ float sB[TCH][Nst];
    for (int idx = e; idx < TCH * Nst; idx += 256) {
        int tl = idx >> 4, n = idx & 15;
        sB[tl][n] = (t0 + tl < Lq) ? dbl[(size_t)(t0 + tl) * 40 + 8 + n] : 0.f;
    }
    __syncthreads();

    float An[Nst];
    const float4* ap = (const float4*)(Alog + e * Nst);
#pragma unroll
    for (int q = 0; q < 4; q++) {
        float4 av = ap[q];
        An[q * 4 + 0] = -__expf(av.x);
        An[q * 4 + 1] = -__expf(av.y);
        An[q * 4 + 2] = -__expf(av.z);
        An[q * 4 + 3] = -__expf(av.w);
    }
    float s[Nst];
#pragma unroll
    for (int n = 0; n < Nst; n++) s[n] = 0.f;
    float sumd = 0.f;

    for (int tl = 0; tl < tn; tl++) {
        int t = t0 + tl;
        float dv = delta[(size_t)t * EDm + e];
        float u = dv * xc[(size_t)t * EDm + e];
        sumd += dv;
        const float4* bp = (const float4*)&sB[tl][0];
        float4 b0 = bp[0], b1 = bp[1], b2 = bp[2], b3 = bp[3];
        float bv[Nst] = {b0.x, b0.y, b0.z, b0.w, b1.x, b1.y, b1.z, b1.w,
                         b2.x, b2.y, b2.z, b2.w, b3.x, b3.y, b3.z, b3.w};
#pragma unroll
        for (int n = 0; n < Nst; n++) {
            float a = __expf(dv * An[n]);
            s[n] = fmaf(a, s[n], u * bv[n]);
        }
    }
    float4* So = (float4*)(Sout + ((size_t)c * EDm + e) * Nst);
#pragma unroll
    for (int q = 0; q < 4; q++)
        So[q] = make_float4(s[q * 4], s[q * 4 + 1], s[q * 4 + 2], s[q * 4 + 3]);
    sumdOut[(size_t)c * EDm + e] = sumd;
}

// ---------------- scan phase 2: sequential over chunks (per (e,n) state) ----------------
__global__ __launch_bounds__(256)
void scan2_kernel(const float* __restrict__ Alog, const float* __restrict__ sumd,
                  const float* __restrict__ S, float* __restrict__ carry)
{
    int idx = blockIdx.x * 256 + threadIdx.x;  // < 4096
    int e = idx >> 4;
    float An = -__expf(Alog[idx]);
    float cur = 0.f;
    for (int c = 0; c < NCH; c++) {
        carry[(size_t)c * (EDm * Nst) + idx] = cur;
        float P = __expf(An * sumd[(size_t)c * EDm + e]);
        cur = fmaf(P, cur, S[(size_t)c * (EDm * Nst) + idx]);
    }
}

// ---------------- scan phase 3: replay with carry-in, produce y ----------------
__global__ __launch_bounds__(256)
void scan3_kernel(const float* __restrict__ delta, const float* __restrict__ xc,
                  const float* __restrict__ z, const float* __restrict__ dbl,
                  const float* __restrict__ Alog, const float* __restrict__ carry,
                  const float* __restrict__ Dp, float* __restrict__ y)
{
    int c = blockIdx.x;
    int e = threadIdx.x;
    int t0 = c * TCH;
    int tn = min(TCH, Lq - t0);

    __shared__ float sB[TCH][Nst];
    __shared__ float sC[TCH][Nst];
    for (int idx = e; idx < TCH * Nst; idx += 256) {
        int tl = idx >> 4, n = idx & 15;
        bool ok = (t0 + tl) < Lq;
        sB[tl][n] = ok ? dbl[(size_t)(t0 + tl) * 40 + 8 + n] : 0.f;
        sC[tl][n] = ok ? dbl[(size_t)(t0 + tl) * 40 + 24 + n] : 0.f;
    }
    __syncthreads();

    float An[Nst];
    const float4* ap = (const float4*)(Alog + e * Nst);
#pragma unroll
    for (int q = 0; q < 4; q++) {
        float4 av = ap[q];
        An[q * 4 + 0] = -__expf(av.x);
        An[q * 4 + 1] = -__expf(av.y);
        An[q * 4 + 2] = -__expf(av.z);
        An[q * 4 + 3] = -__expf(av.w);
    }
    float s[Nst];
    const float4* cp = (const float4*)(carry + ((size_t)c * EDm + e) * Nst);
#pragma unroll
    for (int q = 0; q < 4; q++) {
        float4 cv = cp[q];
        s[q * 4 + 0] = cv.x; s[q * 4 + 1] = cv.y;
        s[q * 4 + 2] = cv.z; s[q * 4 + 3] = cv.w;
    }
    float dpv = Dp[e];

    for (int tl = 0; tl < tn; tl++) {
        int t = t0 + tl;
        float dv  = delta[(size_t)t * EDm + e];
        float xcv = xc[(size_t)t * EDm + e];
        float zv  = z[(size_t)t * EDm + e];
        float u = dv * xcv;
        const float4* bp = (const float4*)&sB[tl][0];
        const float4* ccp = (const float4*)&sC[tl][0];
        float4 b0 = bp[0], b1 = bp[1], b2 = bp[2], b3 = bp[3];
        float4 c0 = ccp[0], c1 = ccp[1], c2 = ccp[2], c3 = ccp[3];
        float bv[Nst] = {b0.x, b0.y, b0.z, b0.w, b1.x, b1.y, b1.z, b1.w,
                         b2.x, b2.y, b2.z, b2.w, b3.x, b3.y, b3.z, b3.w};
        float cv[Nst] = {c0.x, c0.y, c0.z, c0.w, c1.x, c1.y, c1.z, c1.w,
                         c2.x, c2.y, c2.z, c2.w, c3.x, c3.y, c3.z, c3.w};
        float yy = 0.f;
#pragma unroll
        for (int n = 0; n < Nst; n++) {
            float a = __expf(dv * An[n]);
            s[n] = fmaf(a, s[n], u * bv[n]);
            yy = fmaf(s[n], cv[n], yy);
        }
        float sz = siluf(zv);
        y[(size_t)t * EDm + e] = (yy + dpv * xcv) * sz;
    }
}

// ---------------- attention score: a[t] = sum_d tanh_mat[t][d]*w2[d] + b2 ----------------
__global__ __launch_bounds__(256)
void att2_kernel(const float* __restrict__ ta, const float* __restrict__ w2,
                 const float* __restrict__ b2, float* __restrict__ att)
{
    int r = blockIdx.x * 8 + (threadIdx.x >> 5);
    int lane = threadIdx.x & 31;
    if (r >= Lq) return;
    float acc = 0.f;
#pragma unroll
    for (int q = 0; q < 4; q++)
        acc = fmaf(ta[(size_t)r * Dm + lane + q * 32], w2[lane + q * 32], acc);
#pragma unroll
    for (int o = 16; o > 0; o >>= 1) acc += __shfl_xor_sync(0xffffffffu, acc, o);
    if (lane == 0) att[r] = acc + b2[0];
}

// ---------------- softmax stats over L (max, sumexp) ----------------
__global__ __launch_bounds__(1024)
void stat_kernel(const float* __restrict__ att, float* __restrict__ stat)
{
    int tid = threadIdx.x;
    int lane = tid & 31, wid = tid >> 5;
    __shared__ float sm[32];
    __shared__ float bc;

    float mx = -3.4e38f;
    for (int i = tid; i < Lq; i += 1024) mx = fmaxf(mx, att[i]);
#pragma unroll
    for (int o = 16; o > 0; o >>= 1) mx = fmaxf(mx, __shfl_xor_sync(0xffffffffu, mx, o));
    if (lane == 0) sm[wid] = mx;
    __syncthreads();
    if (tid == 0) {
        float m = sm[0];
        for (int i = 1; i < 32; i++) m = fmaxf(m, sm[i]);
        bc = m;
    }
    __syncthreads();
    float M = bc;

    float s = 0.f;
    for (int i = tid; i < Lq; i += 1024) s += expf(att[i] - M);
#pragma unroll
    for (int o = 16; o > 0; o >>= 1) s += __shfl_xor_sync(0xffffffffu, s, o);
    __syncthreads();
    if (lane == 0) sm[wid] = s;
    __syncthreads();
    if (tid == 0) {
        float S = 0.f;
        for (int i = 0; i < 32; i++) S += sm[i];
        stat[0] = M;
        stat[1] = S;
    }
}

// ---------------- weighted pooling (deterministic two-stage) ----------------
__global__ __launch_bounds__(128)
void pool_kernel(const float* __restrict__ hln, const float* __restrict__ att,
                 const float* __restrict__ stat, float* __restrict__ part)
{
    int d = threadIdx.x;
    int b = blockIdx.x;
    int t0 = b * 128;
    float M = stat[0];
    float inv = 1.f / stat[1];
    float acc = 0.f;
    for (int tl = 0; tl < 128; tl++) {
        int t = t0 + tl;
        if (t < Lq) acc = fmaf(expf(att[t] - M), hln[(size_t)t * Dm + d], acc);
    }
    part[b * Dm + d] = acc * inv;
}

// ---------------- finalize: pooled -> logits -> softmax/argmax -> output ----------------
__global__ __launch_bounds__(128)
void finalize_kernel(const float* __restrict__ part, const float* __restrict__ clsw,
                     const float* __restrict__ clsb, float* __restrict__ out, int out_size)
{
    __shared__ float spool[Dm];
    __shared__ float sl[2];
    int d = threadIdx.x;
    float acc = 0.f;
    for (int b = 0; b < NPOOL; b++) acc += part[b * Dm + d];
    spool[d] = acc;
    __syncthreads();
    if (d < 2) {
        float lv = clsb[d];
        for (int k = 0; k < Dm; k++) lv = fmaf(spool[k], clsw[k * 2 + d], lv);
        sl[d] = lv;
    }
    __syncthreads();
    if (d == 0) {
        float l0 = sl[0], l1 = sl[1];
        float m = fmaxf(l0, l1);
        float e0 = expf(l0 - m), e1 = expf(l1 - m);
        float inv = 1.f / (e0 + e1);
        float yhat = (l1 > l0) ? 1.f : 0.f;
        if (out_size > 0) out[0] = l0;
        if (out_size > 1) out[1] = l1;
        if (out_size > 2) out[2] = e0 * inv;
        if (out_size > 3) out[3] = e1 * inv;
        if (out_size > 4) out[4] = yhat;
    }
    for (int i = 5 + d; i < out_size; i += 128) out[i] = 0.f;
}

// ---------------- host launcher ----------------
extern "C" void kernel_launch(void* const* d_in, const int* in_sizes, int n_in,
                              void* d_out, int out_size)
{
    const float* x       = (const float*)d_in[0];
    // d_in[1] = coords (unused by reference)
    const float* fc1_w   = (const float*)d_in[2];
    const float* fc1_b   = (const float*)d_in[3];
    const float* rms_w   = (const float*)d_in[4];
    const float* inproj  = (const float*)d_in[5];
    const float* conv_w  = (const float*)d_in[6];
    const float* conv_b  = (const float*)d_in[7];
    const float* xproj   = (const float*)d_in[8];
    const float* dt_w    = (const float*)d_in[9];
    const float* dt_b    = (const float*)d_in[10];
    const float* A_log   = (const float*)d_in[11];
    const float* D_p     = (const float*)d_in[12];
    const float* outproj = (const float*)d_in[13];
    const float* ln_w    = (const float*)d_in[14];
    const float* ln_b    = (const float*)d_in[15];
    const float* att_w1  = (const float*)d_in[16];
    const float* att_b1  = (const float*)d_in[17];
    const float* att_w2  = (const float*)d_in[18];
    const float* att_b2  = (const float*)d_in[19];
    const float* cls_w   = (const float*)d_in[20];
    const float* cls_b   = (const float*)d_in[21];

    float *ph, *phn, *phln, *pxb, *pz, *pxc, *pdbl, *pdelta, *py, *pta, *patt;
    float *pS, *psumd, *pcarry, *ppart, *pstat;
    cudaGetSymbolAddress((void**)&ph,     g_h);
    cudaGetSymbolAddress((void**)&phn,    g_hn);
    cudaGetSymbolAddress((void**)&phln,   g_hln);
    cudaGetSymbolAddress((void**)&pxb,    g_xb);
    cudaGetSymbolAddress((void**)&pz,     g_z);
    cudaGetSymbolAddress((void**)&pxc,    g_xc);
    cudaGetSymbolAddress((void**)&pdbl,   g_dbl);
    cudaGetSymbolAddress((void**)&pdelta, g_delta);
    cudaGetSymbolAddress((void**)&py,     g_y);
    cudaGetSymbolAddress((void**)&pta,    g_ta);
    cudaGetSymbolAddress((void**)&patt,   g_att);
    cudaGetSymbolAddress((void**)&pS,     g_S);
    cudaGetSymbolAddress((void**)&psumd,  g_sumd);
    cudaGetSymbolAddress((void**)&pcarry, g_carry);
    cudaGetSymbolAddress((void**)&ppart,  g_part);
    cudaGetSymbolAddress((void**)&pstat,  g_stat);

    const int MB = (Lq + 63) / 64;  // 188

    // h = gelu(x @ fc1_w + fc1_b)
    gemm64<<<dim3(Dm / 64, MB), 128>>>(x, fc1_w, fc1_b, ph, nullptr, Lq, Dm, INDIM, 1);

    for (int l = 0; l < 2; l++) {
        rmsnorm_kernel<<<Lq, 128>>>(ph, rms_w + l * Dm, phn);
        gemm64<<<dim3(512 / 64, MB), 128>>>(phn, inproj + (size_t)l * Dm * 2 * EDm,
                                            nullptr, pxb, pz, Lq, 512, Dm, 2);
        conv_kernel<<<Lq, 256>>>(pxb, conv_w + l * EDm * 4, conv_b + l * EDm, pxc);
        gemm64<<<dim3(1, MB), 128>>>(pxc, xproj + (size_t)l * EDm * 40,
                                     nullptr, pdbl, nullptr, Lq, 40, EDm, 0);
        dt_kernel<<<Lq, 256>>>(pdbl, dt_w + l * DTm * EDm, dt_b + l * EDm, pdelta);
        scan1_kernel<<<NCH, 256>>>(pdelta, pxc, pdbl, A_log + l * EDm * Nst, pS, psumd);
        scan2_kernel<<<16, 256>>>(A_log + l * EDm * Nst, psumd, pS, pcarry);
        scan3_kernel<<<NCH, 256>>>(pdelta, pxc, pz, pdbl, A_log + l * EDm * Nst,
                                   pcarry, D_p + l * EDm, py);
        gemm64<<<dim3(Dm / 64, MB), 128>>>(py, outproj + (size_t)l * EDm * Dm,
                                           nullptr, ph, nullptr, Lq, Dm, EDm, 3);
    }

    layernorm_kernel<<<Lq, 128>>>(ph, ln_w, ln_b, phln);
    gemm64<<<dim3(Dm / 64, MB), 128>>>(phln, att_w1, att_b1, pta, nullptr, Lq, Dm, Dm, 4);
    att2_kernel<<<(Lq + 7) / 8, 256>>>(pta, att_w2, att_b2, patt);
    stat_kernel<<<1, 1024>>>(patt, pstat);
    pool_kernel<<<NPOOL, 128>>>(phln, patt, pstat, ppart);
    finalize_kernel<<<1, 128>>>(ppart, cls_w, cls_b, (float*)d_out, out_size);
}